// round 2
// baseline (speedup 1.0000x reference)
#include <cuda_runtime.h>
#include <cstdint>

typedef unsigned long long ull;

// Packed 2xFP32 FMA — only reachable via PTX fma.rn.f32x2 (ptxas never auto-fuses).
__device__ __forceinline__ ull ffma2(ull a, ull b, ull c) {
    ull d;
    asm("fma.rn.f32x2 %0, %1, %2, %3;" : "=l"(d) : "l"(a), "l"(b), "l"(c));
    return d;
}
__device__ __forceinline__ ull pk2(float a, float b) {
    ull r;
    unsigned ua = __float_as_uint(a), ub = __float_as_uint(b);
    asm("mov.b64 %0, {%1, %2};" : "=l"(r) : "r"(ua), "r"(ub));
    return r;
}
__device__ __forceinline__ float lo2(ull v) { return __uint_as_float((unsigned)(v & 0xffffffffull)); }
__device__ __forceinline__ float hi2(ull v) { return __uint_as_float((unsigned)(v >> 32)); }

#define BATCH 16
#define CIN   64
#define HD    128
#define WD    128
#define OC    128
#define CI    4          // input channels staged per K-iter
#define XROW  132        // padded smem row stride (16B-aligned float4 reads)
#define WROW  132

__global__ __launch_bounds__(256, 2)
void patchconv_kernel(const float* __restrict__ x, const float* __restrict__ wt,
                      const float* __restrict__ bias, float* __restrict__ out) {
    __shared__ __align__(16) float xs[3 * CI * XROW];   // 3 rows x CI ch x 130(+pad)
    __shared__ __align__(16) float ws[36 * WROW];       // (ci*9+r) x 128 o
    __shared__ __align__(16) float ssum[WD];            // patch_sum for this (b,h) row

    const int h   = blockIdx.x;
    const int b   = blockIdx.y;
    const int tid = threadIdx.x;
    const int og  = tid >> 4;      // 0..15 -> o-group
    const int wg  = tid & 15;      // 0..15 -> w-group
    const int o0  = og << 3;
    const int w0  = wg << 3;

    ull acc[4][8];                 // 4 o-pairs (8 o) x 8 w, packed fp32x2 over o
    #pragma unroll
    for (int i = 0; i < 4; i++)
        #pragma unroll
        for (int j = 0; j < 8; j++) acc[i][j] = 0ull;

    float s[8];                    // patch_sum partials (og==0 threads only)
    #pragma unroll
    for (int j = 0; j < 8; j++) s[j] = 0.f;

    const float* xb = x + (size_t)b * CIN * HD * WD;

    #pragma unroll 1
    for (int ci0 = 0; ci0 < CIN; ci0 += CI) {
        __syncthreads();
        // ---- stage x: rows h-1..h+1, CI channels, width padded to 130 ----
        for (int idx = tid; idx < 3 * CI * 130; idx += 256) {
            int kh  = idx / (CI * 130);
            int rem = idx - kh * (CI * 130);
            int ci  = rem / 130;
            int t   = rem - ci * 130;
            int hr  = h - 1 + kh;
            int wg_ = t - 1;
            float v = 0.f;
            if ((unsigned)hr < (unsigned)HD && (unsigned)wg_ < (unsigned)WD)
                v = xb[((size_t)(ci0 + ci) * HD + hr) * WD + wg_];
            xs[(kh * CI + ci) * XROW + t] = v;
        }
        // ---- stage weights: f = ci*9 + r (36 taps), o-contiguous rows ----
        for (int idx = tid; idx < 36 * OC; idx += 256) {
            int o = idx / 36;
            int f = idx - o * 36;
            ws[f * WROW + o] = wt[o * (CIN * 9) + ci0 * 9 + f];
        }
        __syncthreads();

        #pragma unroll
        for (int ci = 0; ci < CI; ci++) {
            #pragma unroll
            for (int kh = 0; kh < 3; kh++) {
                const float* xr = &xs[(kh * CI + ci) * XROW + w0];
                float4 a0 = *(const float4*)(xr);
                float4 a1 = *(const float4*)(xr + 4);
                float2 a2 = *(const float2*)(xr + 8);
                float xv[10] = {a0.x, a0.y, a0.z, a0.w,
                                a1.x, a1.y, a1.z, a1.w,
                                a2.x, a2.y};
                ull xp[10];
                #pragma unroll
                for (int t = 0; t < 10; t++) xp[t] = pk2(xv[t], xv[t]);

                if (og == 0) {   // patch_sum rides along on the same staged data
                    #pragma unroll
                    for (int j = 0; j < 8; j++) s[j] += xv[j] + xv[j + 1] + xv[j + 2];
                }

                #pragma unroll
                for (int kw = 0; kw < 3; kw++) {
                    const ulonglong2* wr =
                        (const ulonglong2*)&ws[(ci * 9 + kh * 3 + kw) * WROW + o0];
                    ulonglong2 p0 = wr[0];
                    ulonglong2 p1 = wr[1];
                    ull wp[4] = {p0.x, p0.y, p1.x, p1.y};
                    #pragma unroll
                    for (int i = 0; i < 4; i++)
                        #pragma unroll
                        for (int j = 0; j < 8; j++)
                            acc[i][j] = ffma2(wp[i], xp[j + kw], acc[i][j]);
                }
            }
        }
    }

    // ---- broadcast patch_sum across o-groups ----
    if (og == 0) {
        #pragma unroll
        for (int j = 0; j < 8; j++) ssum[w0 + j] = s[j];
    }
    __syncthreads();

    float cj[8];
    #pragma unroll
    for (int j = 0; j < 8; j++)
        cj[j] = 0.1f * (float)(h + w0 + j) * ssum[w0 + j];

    // ---- epilogue: unpack, add rank-1 term + bias, coalesced float4 stores ----
    #pragma unroll
    for (int i = 0; i < 4; i++) {
        #pragma unroll
        for (int half = 0; half < 2; half++) {
            int o = o0 + 2 * i + half;
            float bz = bias[o];
            float r[8];
            #pragma unroll
            for (int j = 0; j < 8; j++) {
                float p = half ? hi2(acc[i][j]) : lo2(acc[i][j]);
                r[j] = p + cj[j] + bz;
            }
            float* ob = out + (((size_t)b * OC + o) * HD + h) * WD + w0;
            *(float4*)(ob)     = make_float4(r[0], r[1], r[2], r[3]);
            *(float4*)(ob + 4) = make_float4(r[4], r[5], r[6], r[7]);
        }
    }
}

extern "C" void kernel_launch(void* const* d_in, const int* in_sizes, int n_in,
                              void* d_out, int out_size) {
    const float* x    = (const float*)d_in[0];
    const float* wt   = (const float*)d_in[1];
    const float* bias = (const float*)d_in[2];
    float* out        = (float*)d_out;
    dim3 grid(HD, BATCH);   // one CTA per (h, b): 128 x 16 = 2048 CTAs
    patchconv_kernel<<<grid, 256>>>(x, wt, bias, out);
}

// round 4
// speedup vs baseline: 4.1837x; 4.1837x over previous
#include <cuda_runtime.h>
#include <cstdint>

#define HD 128
#define WD 128
#define OC 128
#define CIN 64
#define XST 136                 // padded row stride (floats): 136 % 32 == 8 -> conflict-free frags
#define WBYTES (64 * XST * 4)   // one tap tile: 64 k-rows x 136 floats = 34816 B

// smem byte offsets
#define SM_XS   0               // 4 * 64 * 136 * 4 = 139264
#define SM_W    139264          // 2 * 34816 = 69632
#define SM_CS   208896          // 4 * 136 * 4 = 2176
#define SM_PS   211072          // 2 * 128 * 4 = 1024
#define SM_BIAS 212096          // 512
#define SM_MB   212608          // 2 mbarriers
#define SM_TOT  212640

__device__ __align__(128) float g_Wt[9 * 64 * XST];   // [tap][ci][o(pad 136)] tf32-rounded

// ---------- helpers ----------
__device__ __forceinline__ uint32_t smem_u32(const void* p) {
    uint32_t a;
    asm("{ .reg .u64 t; cvta.to.shared.u64 t, %1; cvt.u32.u64 %0, t; }" : "=r"(a) : "l"(p));
    return a;
}
__device__ __forceinline__ float tf32r(float v) {
    float r; asm("cvt.rna.tf32.f32 %0, %1;" : "=f"(r) : "f"(v)); return r;
}
#define MB_INIT(mb, c)   asm volatile("mbarrier.init.shared.b64 [%0], %1;" :: "r"(mb), "r"((uint32_t)(c)) : "memory")
#define MB_EXPECT(mb, n) asm volatile("mbarrier.arrive.expect_tx.shared.b64 _, [%0], %1;" :: "r"(mb), "r"((uint32_t)(n)) : "memory")
#define BULK_G2S(dst, src, n, mb) \
    asm volatile("cp.async.bulk.shared::cta.global.mbarrier::complete_tx::bytes [%0], [%1], %2, [%3];" \
                 :: "r"(dst), "l"(src), "r"((uint32_t)(n)), "r"(mb) : "memory")
#define MB_WAIT(mb, par) do {                                                          \
    uint32_t _m = (mb), _p = (par), _d;                                                \
    asm volatile("{\n\t.reg .pred p;\n\t"                                              \
        "mbarrier.try_wait.parity.acquire.cta.shared::cta.b64 p, [%1], %2;\n\t"        \
        "selp.b32 %0,1,0,p;\n\t}" : "=r"(_d) : "r"(_m), "r"(_p) : "memory");           \
    if (!_d) {                                                                         \
        asm volatile("{\n\t.reg .pred P1;\n\tWL_%=:\n\t"                               \
            "mbarrier.try_wait.parity.acquire.cta.shared::cta.b64 P1, [%0], %1, 0x989680;\n\t" \
            "@P1 bra.uni WDN_%=;\n\tbra.uni WL_%=;\n\tWDN_%=:\n\t}"                    \
            :: "r"(_m), "r"(_p) : "memory");                                           \
    }                                                                                  \
} while (0)

// m16n8k8 tf32 HMMA (sm_80+ baseline ISA — no 'a'-suffix features)
#define MMA8(d, a, bq)                                                                 \
    asm volatile("mma.sync.aligned.m16n8k8.row.col.f32.tf32.tf32.f32 "                 \
        "{%0,%1,%2,%3}, {%4,%5,%6,%7}, {%8,%9}, {%0,%1,%2,%3};"                        \
        : "+f"((d)[0]), "+f"((d)[1]), "+f"((d)[2]), "+f"((d)[3])                       \
        : "r"(__float_as_uint((a)[0])), "r"(__float_as_uint((a)[1])),                  \
          "r"(__float_as_uint((a)[2])), "r"(__float_as_uint((a)[3])),                  \
          "r"(__float_as_uint((bq)[0])), "r"(__float_as_uint((bq)[1])))

// ---------- prepass: weights -> [tap][ci][o] padded, tf32-rounded ----------
__global__ void prep_w(const float* __restrict__ wt) {
    int i = blockIdx.x * blockDim.x + threadIdx.x;
    if (i >= 9 * 64 * XST) return;
    int tap = i / (64 * XST), r = i % (64 * XST);
    int ci = r / XST, o = r % XST;
    float v = 0.f;
    if (o < 128) v = tf32r(wt[o * 576 + ci * 9 + tap]);   // wt[o][ci][kh][kw], tap = kh*3+kw
    g_Wt[i] = v;
}

// ---------- main kernel: one CTA per (b, h-pair) ----------
__global__ __launch_bounds__(256, 1)
void patchconv_mma(const float* __restrict__ x, const float* __restrict__ bias,
                   float* __restrict__ out) {
    extern __shared__ __align__(16) char smem[];
    float* sxs   = (float*)(smem + SM_XS);    // [r(4)][ci(64)][w(136)], w idx = xcol+4
    float* scs   = (float*)(smem + SM_CS);    // channel sums [r][w]
    float* sps   = (float*)(smem + SM_PS);    // 3x3 patch sums [hl][w]
    float* sbias = (float*)(smem + SM_BIAS);
    const uint32_t sb  = smem_u32(smem);
    const uint32_t mb0 = sb + SM_MB, mb1 = sb + SM_MB + 8;

    const int tid = threadIdx.x, lane = tid & 31, wid = tid >> 5;
    const int h0 = blockIdx.x * 2, b = blockIdx.y;

    if (tid == 0) { MB_INIT(mb0, 1); MB_INIT(mb1, 1); }
    if (tid < 128) sbias[tid] = bias[tid];
    __syncthreads();
    if (tid == 0) { MB_EXPECT(mb0, WBYTES); BULK_G2S(sb + SM_W, (const void*)g_Wt, WBYTES, mb0); }

    // ---- stage x: 4 halo rows, tf32-rounded, zero borders ----
    const float* xb = x + (size_t)b * CIN * HD * WD;
    for (int idx = wid; idx < 4 * 64; idx += 8) {
        int r = idx >> 6, ci = idx & 63;
        int hr = h0 - 1 + r;
        float4 v = make_float4(0.f, 0.f, 0.f, 0.f);
        if ((unsigned)hr < 128u)
            v = *(const float4*)(xb + ((size_t)ci * HD + hr) * WD + lane * 4);
        v.x = tf32r(v.x); v.y = tf32r(v.y); v.z = tf32r(v.z); v.w = tf32r(v.w);
        float* d = sxs + (r * 64 + ci) * XST;
        *(float4*)(d + 4 + lane * 4) = v;
        if (lane < 2) *(float4*)(d + lane * 132) = make_float4(0.f, 0.f, 0.f, 0.f);
    }
    __syncthreads();

    // ---- channel sums + 3x3 patch sums (rank-1 term), fp32 on rounded data ----
    for (int p = tid; p < 4 * XST; p += 256) {
        int r = p / XST, w = p - r * XST;
        float s = 0.f;
        const float* c = sxs + r * 64 * XST + w;
        #pragma unroll 8
        for (int k = 0; k < 64; k++) s += c[k * XST];
        scs[p] = s;
    }
    __syncthreads();
    {
        int hl = tid >> 7, wo = tid & 127;
        float s = 0.f;
        #pragma unroll
        for (int kh = 0; kh < 3; kh++)
            #pragma unroll
            for (int kw = 0; kw < 3; kw++)
                s += scs[(hl + kh) * XST + wo + kw + 3];
        sps[tid] = s;
    }

    // ---- main loop: 9 taps, double-buffered weights, 32 HMMA / k-step / warp ----
    const int warp_m = wid >> 1, warp_n = wid & 1;
    const int hl = warp_m >> 1;
    const int wb = (warp_m & 1) * 64;
    const int ob = warp_n * 64;

    float acc[4][8][4];
    #pragma unroll
    for (int mi = 0; mi < 4; mi++)
        #pragma unroll
        for (int ni = 0; ni < 8; ni++)
            #pragma unroll
            for (int j = 0; j < 4; j++) acc[mi][ni][j] = 0.f;

    #pragma unroll 1
    for (int t = 0; t < 9; t++) {
        const int buf = t & 1;
        if (t < 8 && tid == 0) {
            int nb = buf ^ 1;
            uint32_t m = nb ? mb1 : mb0;
            MB_EXPECT(m, WBYTES);
            BULK_G2S(sb + SM_W + nb * WBYTES, (const void*)(g_Wt + (t + 1) * 64 * XST), WBYTES, m);
        }
        MB_WAIT(buf ? mb1 : mb0, (t >> 1) & 1);

        const int kh = t / 3, kw = t - kh * 3;
        const float* Ab = sxs + (hl + kh) * 64 * XST + (lane & 3) * XST + wb + kw + 3 + (lane >> 2);
        const float* Bb = (const float*)(smem + SM_W + buf * WBYTES) + (lane & 3) * XST + ob + (lane >> 2);

        #pragma unroll
        for (int s = 0; s < 8; s++) {
            const float* Ap = Ab + s * 8 * XST;
            const float* Bp = Bb + s * 8 * XST;
            float a[4][4], bq[8][2];
            #pragma unroll
            for (int mi = 0; mi < 4; mi++) {
                a[mi][0] = Ap[mi * 16];
                a[mi][1] = Ap[mi * 16 + 8];
                a[mi][2] = Ap[mi * 16 + 4 * XST];
                a[mi][3] = Ap[mi * 16 + 8 + 4 * XST];
            }
            #pragma unroll
            for (int ni = 0; ni < 8; ni++) {
                bq[ni][0] = Bp[ni * 8];
                bq[ni][1] = Bp[ni * 8 + 4 * XST];
            }
            #pragma unroll
            for (int mi = 0; mi < 4; mi++)
                #pragma unroll
                for (int ni = 0; ni < 8; ni++)
                    MMA8(acc[mi][ni], a[mi], bq[ni]);
        }
        __syncthreads();   // all warps done with buf before it is refilled at t+2
    }

    // ---- epilogue: + bias[o] + 0.1*(h+w)*patch_sum, 32B-sector-aligned stores ----
    const int hg = h0 + hl;
    float* outb = out + (size_t)b * OC * HD * WD + (size_t)hg * WD;
    #pragma unroll
    for (int mi = 0; mi < 4; mi++) {
        int w0r = wb + mi * 16 + (lane >> 2);
        float c0 = 0.1f * (float)(hg + w0r) * sps[hl * 128 + w0r];
        float c1 = 0.1f * (float)(hg + w0r + 8) * sps[hl * 128 + w0r + 8];
        #pragma unroll
        for (int ni = 0; ni < 8; ni++) {
            int o = ob + ni * 8 + (lane & 3) * 2;
            float bz0 = sbias[o], bz1 = sbias[o + 1];
            float* p0 = outb + (size_t)o * (HD * WD);
            float* p1 = p0 + HD * WD;
            p0[w0r]     = acc[mi][ni][0] + c0 + bz0;
            p1[w0r]     = acc[mi][ni][1] + c0 + bz1;
            p0[w0r + 8] = acc[mi][ni][2] + c1 + bz0;
            p1[w0r + 8] = acc[mi][ni][3] + c1 + bz1;
        }
    }
}

extern "C" void kernel_launch(void* const* d_in, const int* in_sizes, int n_in,
                              void* d_out, int out_size) {
    const float* x    = (const float*)d_in[0];
    const float* wt   = (const float*)d_in[1];
    const float* bias = (const float*)d_in[2];
    float* out        = (float*)d_out;
    cudaFuncSetAttribute(patchconv_mma, cudaFuncAttributeMaxDynamicSharedMemorySize, SM_TOT);
    prep_w<<<(9 * 64 * XST + 255) / 256, 256>>>(wt);
    patchconv_mma<<<dim3(64, 16), 256, SM_TOT>>>(x, bias, out);
}